// round 9
// baseline (speedup 1.0000x reference)
#include <cuda_runtime.h>
#include <math.h>

// Problem shapes
#define HH   51          // hidden size
#define HP   52          // padded hidden (pad unit h=51 is inert: zero weights)
#define GPT  208         // gate-interleaved weight row stride = HP*4 floats
#define K1   52          // layer-1 K (padded)
#define K2   104         // layer-2 K: [h1 pad HP][h2 pad HP]
#define SST  36          // state row stride (floats): 144B, 16B-aligned, conflict-free stores
#define NSEQ 16          // sequences per block
#define NT   208         // threads: 52 hidden x 4 seq-quads
#define NBLK 128
#define TSZ  2048
#define XCH  64          // I/O staging chunk

// shared layout (floats)
#define OFF_W1 0                        // [K1][HP][4] gate-interleaved
#define OFF_W2 (OFF_W1 + K1*GPT)       // [K2][HP][4]
#define OFF_S0 (OFF_W2 + K2*GPT)       // state buf0: [K2][SST], value duplicated pairs (h,h)
#define OFF_S1 (OFF_S0 + K2*SST)       // state buf1
#define OFF_X  (OFF_S1 + K2*SST)       // [16][64]
#define OFF_Y  (OFF_X  + NSEQ*XCH)     // [16][64]
#define OFF_WL (OFF_Y  + NSEQ*XCH)     // [52]: [0..50]=W_lin, [51]=b_lin
#define SMEM_FLOATS (OFF_WL + 52)

typedef unsigned long long u64;

__device__ __forceinline__ u64 pack2(float a, float b) {
    u64 d; asm("mov.b64 %0,{%1,%2};" : "=l"(d) : "f"(a), "f"(b)); return d;
}
__device__ __forceinline__ void unpack2(u64 v, float &a, float &b) {
    asm("mov.b64 {%0,%1},%2;" : "=f"(a), "=f"(b) : "l"(v));
}
__device__ __forceinline__ u64 ffma2(u64 a, u64 b, u64 c) {
    u64 d; asm("fma.rn.f32x2 %0,%1,%2,%3;" : "=l"(d) : "l"(a), "l"(b), "l"(c)); return d;
}

__device__ __forceinline__ float fsig(float x) {
    float e = __expf(fminf(-x, 80.f));
    return __fdividef(1.f, 1.f + e);
}
__device__ __forceinline__ float ftanh_f(float x) {
    float ax = fabsf(x);
    float e  = __expf(-2.f * ax);
    float t  = __fdividef(1.f - e, 1.f + e);
    return x >= 0.f ? t : -t;
}
__device__ __forceinline__ float lstm_act(u64 aif, u64 ago, float &c) {
    float gi, gf, gg, go;
    unpack2(aif, gi, gf);
    unpack2(ago, gg, go);
    float cn = fsig(gf) * c + fsig(gi) * ftanh_f(gg);
    c = cn;
    return fsig(go) * ftanh_f(cn);
}

__global__ __launch_bounds__(NT, 1)
void lstm2_kernel(const float* __restrict__ in,
                  const float* __restrict__ W_ih1,
                  const float* __restrict__ W_hh1,
                  const float* __restrict__ b_ih1,
                  const float* __restrict__ b_hh1,
                  const float* __restrict__ W_ih2,
                  const float* __restrict__ W_hh2,
                  const float* __restrict__ b_ih2,
                  const float* __restrict__ b_hh2,
                  const float* __restrict__ W_lin,
                  const float* __restrict__ b_lin,
                  float* __restrict__ out)
{
    extern __shared__ float sm[];
    float* sW1 = sm + OFF_W1;
    float* sW2 = sm + OFF_W2;
    float* sX  = sm + OFF_X;
    float* sY  = sm + OFF_Y;
    float* sWl = sm + OFF_WL;

    const int tid  = threadIdx.x;
    const int seq0 = blockIdx.x * NSEQ;

    // ---- one-time shared init: gate-interleaved k-major weights ----
    for (int i = tid; i < K1*GPT; i += NT) {
        int k = i / GPT, r = i % GPT, hh = r >> 2, q = r & 3;
        sW1[i] = (k < HH && hh < HH) ? W_hh1[(q*HH + hh)*HH + k] : 0.f;
    }
    for (int i = tid; i < K2*GPT; i += NT) {
        int k = i / GPT, r = i % GPT, hh = r >> 2, q = r & 3;
        float v = 0.f;
        if (hh < HH) {
            if (k < HH)                    v = W_ih2[(q*HH + hh)*HH + k];        // input = h1
            else if (k >= HP && k < HP+HH) v = W_hh2[(q*HH + hh)*HH + (k - HP)]; // recurrent h2
        }
        sW2[i] = v;
    }
    for (int i = tid; i < 2*K2*SST; i += NT) sm[OFF_S0 + i] = 0.f;  // both state buffers
    for (int i = tid; i < 52; i += NT)
        sWl[i] = (i < HH) ? W_lin[i] : b_lin[0];

    // ---- per-thread tile: hidden h, seqs s0..s0+3 ----
    const int h    = tid >> 2;        // 0..51 (51 = inert pad)
    const int s0   = (tid & 3) * 4;
    const int h4   = h * 4;
    const int s02  = s0 * 2;          // float offset of dup-pair block

    // per-thread constants (registers, held across all 2048 steps)
    u64 wi_if, wi_go, b1_if, b1_go, b2_if, b2_go;
    {
        const bool ok = (h < HH);
        float w0 = ok ? W_ih1[0*HH + h] : 0.f;
        float w1 = ok ? W_ih1[1*HH + h] : 0.f;
        float w2 = ok ? W_ih1[2*HH + h] : 0.f;
        float w3 = ok ? W_ih1[3*HH + h] : 0.f;
        wi_if = pack2(w0, w1); wi_go = pack2(w2, w3);
        float a0 = ok ? b_ih1[0*HH + h] + b_hh1[0*HH + h] : 0.f;
        float a1 = ok ? b_ih1[1*HH + h] + b_hh1[1*HH + h] : 0.f;
        float a2 = ok ? b_ih1[2*HH + h] + b_hh1[2*HH + h] : 0.f;
        float a3 = ok ? b_ih1[3*HH + h] + b_hh1[3*HH + h] : 0.f;
        b1_if = pack2(a0, a1); b1_go = pack2(a2, a3);
        float c0 = ok ? b_ih2[0*HH + h] + b_hh2[0*HH + h] : 0.f;
        float d1 = ok ? b_ih2[1*HH + h] + b_hh2[1*HH + h] : 0.f;
        float c2v = ok ? b_ih2[2*HH + h] + b_hh2[2*HH + h] : 0.f;
        float c3 = ok ? b_ih2[3*HH + h] + b_hh2[3*HH + h] : 0.f;
        b2_if = pack2(c0, d1); b2_go = pack2(c2v, c3);
    }

    float c1[4] = {0.f, 0.f, 0.f, 0.f};
    float c2[4] = {0.f, 0.f, 0.f, 0.f};

    // ping-pong state buffers: sR holds prior-step state, sWb receives this step's
    float* sR  = sm + OFF_S0;
    float* sWb = sm + OFF_S1;

    for (int t = 0; t < TSZ; t++) {
        const int tin = t & (XCH - 1);
        if (tin == 0) {
            __syncthreads();                       // init done (t=0) / sY complete
            if (t) {
                const int tp = t - XCH;
                for (int i = tid; i < NSEQ*XCH; i += NT) {
                    int s = i >> 6, j = i & 63;
                    out[(size_t)(seq0 + s) * TSZ + tp + j] = sY[i];
                }
            }
            for (int i = tid; i < NSEQ*XCH; i += NT) {
                int s = i >> 6, j = i & 63;
                sX[i] = in[(size_t)(seq0 + s) * TSZ + t + j];
            }
            __syncthreads();
        }

        // ===== Layer 1: fused matvec + activation (no intermediate sync) =====
        {
            u64 aif[4], ago[4];
            #pragma unroll
            for (int si = 0; si < 4; si++) {
                float x = sX[(s0 + si)*XCH + tin];
                u64 xx = pack2(x, x);
                aif[si] = ffma2(wi_if, xx, b1_if);
                ago[si] = ffma2(wi_go, xx, b1_go);
            }
            #pragma unroll 4
            for (int k = 0; k < K1; k++) {
                ulonglong2 w  = *(const ulonglong2*)(sW1 + k*GPT + h4);
                ulonglong2 ha = *(const ulonglong2*)(sR + k*SST + s02);
                ulonglong2 hb = *(const ulonglong2*)(sR + k*SST + s02 + 4);
                aif[0] = ffma2(w.x, ha.x, aif[0]); ago[0] = ffma2(w.y, ha.x, ago[0]);
                aif[1] = ffma2(w.x, ha.y, aif[1]); ago[1] = ffma2(w.y, ha.y, ago[1]);
                aif[2] = ffma2(w.x, hb.x, aif[2]); ago[2] = ffma2(w.y, hb.x, ago[2]);
                aif[3] = ffma2(w.x, hb.y, aif[3]); ago[3] = ffma2(w.y, hb.y, ago[3]);
            }
            #pragma unroll
            for (int si = 0; si < 4; si++) {
                float hv = lstm_act(aif[si], ago[si], c1[si]);
                *(float2*)(sWb + h*SST + (s0 + si)*2) = make_float2(hv, hv);
            }
        }
        __syncthreads();   // h1(t) visible

        // ===== Layer 2: K=104 over [h1(t) | h2(t-1)] =====
        {
            u64 aif[4] = {b2_if, b2_if, b2_if, b2_if};
            u64 ago[4] = {b2_go, b2_go, b2_go, b2_go};
            #pragma unroll 4
            for (int k = 0; k < K1; k++) {                    // h1(t) from write buffer
                ulonglong2 w  = *(const ulonglong2*)(sW2 + k*GPT + h4);
                ulonglong2 ha = *(const ulonglong2*)(sWb + k*SST + s02);
                ulonglong2 hb = *(const ulonglong2*)(sWb + k*SST + s02 + 4);
                aif[0] = ffma2(w.x, ha.x, aif[0]); ago[0] = ffma2(w.y, ha.x, ago[0]);
                aif[1] = ffma2(w.x, ha.y, aif[1]); ago[1] = ffma2(w.y, ha.y, ago[1]);
                aif[2] = ffma2(w.x, hb.x, aif[2]); ago[2] = ffma2(w.y, hb.x, ago[2]);
                aif[3] = ffma2(w.x, hb.y, aif[3]); ago[3] = ffma2(w.y, hb.y, ago[3]);
            }
            #pragma unroll 4
            for (int k = K1; k < K2; k++) {                   // h2(t-1) from read buffer
                ulonglong2 w  = *(const ulonglong2*)(sW2 + k*GPT + h4);
                ulonglong2 ha = *(const ulonglong2*)(sR + k*SST + s02);
                ulonglong2 hb = *(const ulonglong2*)(sR + k*SST + s02 + 4);
                aif[0] = ffma2(w.x, ha.x, aif[0]); ago[0] = ffma2(w.y, ha.x, ago[0]);
                aif[1] = ffma2(w.x, ha.y, aif[1]); ago[1] = ffma2(w.y, ha.y, ago[1]);
                aif[2] = ffma2(w.x, hb.x, aif[2]); ago[2] = ffma2(w.y, hb.x, ago[2]);
                aif[3] = ffma2(w.x, hb.y, aif[3]); ago[3] = ffma2(w.y, hb.y, ago[3]);
            }
            #pragma unroll
            for (int si = 0; si < 4; si++) {
                float hv = lstm_act(aif[si], ago[si], c2[si]);
                *(float2*)(sWb + (HP + h)*SST + (s0 + si)*2) = make_float2(hv, hv);
            }
        }
        __syncthreads();   // h2(t) visible

        // ===== output: y = h2 . W_lin + b_lin (warps 0-1; overlaps next step for others) =====
        if (tid < 64) {
            int s = tid >> 2, pq = tid & 3;
            float acc = 0.f;
            #pragma unroll
            for (int k = pq; k < HH; k += 4)
                acc += sWb[(HP + k)*SST + s*2] * sWl[k];
            acc += __shfl_xor_sync(0xffffffffu, acc, 1);
            acc += __shfl_xor_sync(0xffffffffu, acc, 2);
            if (pq == 0) sY[s*XCH + tin] = acc + sWl[HH];
        }

        { float* tp_ = sR; sR = sWb; sWb = tp_; }
    }

    __syncthreads();
    {
        const int tp = TSZ - XCH;
        for (int i = tid; i < NSEQ*XCH; i += NT) {
            int s = i >> 6, j = i & 63;
            out[(size_t)(seq0 + s) * TSZ + tp + j] = sY[i];
        }
    }
}

extern "C" void kernel_launch(void* const* d_in, const int* in_sizes, int n_in,
                              void* d_out, int out_size) {
    (void)in_sizes; (void)n_in; (void)out_size;
    const float* in    = (const float*)d_in[0];
    const float* W_ih1 = (const float*)d_in[1];
    const float* W_hh1 = (const float*)d_in[2];
    const float* b_ih1 = (const float*)d_in[3];
    const float* b_hh1 = (const float*)d_in[4];
    const float* W_ih2 = (const float*)d_in[5];
    const float* W_hh2 = (const float*)d_in[6];
    const float* b_ih2 = (const float*)d_in[7];
    const float* b_hh2 = (const float*)d_in[8];
    const float* W_lin = (const float*)d_in[9];
    const float* b_lin = (const float*)d_in[10];
    float* out = (float*)d_out;

    const size_t smem = (size_t)SMEM_FLOATS * sizeof(float);   // ~165 KB
    cudaFuncSetAttribute(lstm2_kernel,
                         cudaFuncAttributeMaxDynamicSharedMemorySize, (int)smem);
    lstm2_kernel<<<NBLK, NT, smem>>>(in, W_ih1, W_hh1, b_ih1, b_hh1,
                                     W_ih2, W_hh2, b_ih2, b_hh2,
                                     W_lin, b_lin, out);
}